// round 8
// baseline (speedup 1.0000x reference)
#include <cuda_runtime.h>
#include <cuda_bf16.h>
#include <cstdint>

#define MAX_NODES 100000
#define MAX_EDGES 1600000
#define D 64
#define D4 (D / 4)

typedef unsigned long long u64t;

// ---------------------------------------------------------------------------
// Scratch (allocation-free rule -> device globals). All int; no float atomics.
// ---------------------------------------------------------------------------
__device__ int g_deg[MAX_NODES];
__device__ int g_off[MAX_NODES];
__device__ int g_cursor[MAX_NODES];
__device__ int g_bsum[1024];
__device__ int g_elist[MAX_EDGES];

// packed f32x2 FMA: acc.lo += a.lo*b.lo ; acc.hi += a.hi*b.hi
__device__ __forceinline__ void ffma2(u64t& acc, u64t a, u64t b) {
    asm("fma.rn.f32x2 %0, %1, %2, %0;" : "+l"(acc) : "l"(a), "l"(b));
}

// ---------------------------------------------------------------------------
// K1: zero degree counters
// ---------------------------------------------------------------------------
__global__ void zero_deg(int n) {
    int i = blockIdx.x * blockDim.x + threadIdx.x;
    if (i < n) g_deg[i] = 0;
}

// ---------------------------------------------------------------------------
// K2: count in-degree per dst (int32 indices)
// ---------------------------------------------------------------------------
__global__ void count_deg(const int* __restrict__ dst, int e) {
    int i = blockIdx.x * blockDim.x + threadIdx.x;
    if (i < e) atomicAdd(&g_deg[dst[i]], 1);
}

// ---------------------------------------------------------------------------
// K3a/b/c: exclusive scan of g_deg -> g_off  (1024 items per block)
// ---------------------------------------------------------------------------
__global__ __launch_bounds__(1024) void scan_blocks(int n) {
    __shared__ int s[1024];
    int tid = threadIdx.x;
    int i = blockIdx.x * 1024 + tid;
    int v = (i < n) ? g_deg[i] : 0;
    s[tid] = v;
    __syncthreads();
#pragma unroll
    for (int ofs = 1; ofs < 1024; ofs <<= 1) {
        int t = (tid >= ofs) ? s[tid - ofs] : 0;
        __syncthreads();
        s[tid] += t;
        __syncthreads();
    }
    if (i < n) g_off[i] = s[tid] - v;            // exclusive
    if (tid == 1023) g_bsum[blockIdx.x] = s[1023];
}

__global__ __launch_bounds__(1024) void scan_bsums(int nb) {
    __shared__ int s[1024];
    int tid = threadIdx.x;
    int v = (tid < nb) ? g_bsum[tid] : 0;
    s[tid] = v;
    __syncthreads();
#pragma unroll
    for (int ofs = 1; ofs < 1024; ofs <<= 1) {
        int t = (tid >= ofs) ? s[tid - ofs] : 0;
        __syncthreads();
        s[tid] += t;
        __syncthreads();
    }
    if (tid < nb) g_bsum[tid] = s[tid] - v;      // exclusive block offsets
}

__global__ void scan_add(int n) {
    int i = blockIdx.x * blockDim.x + threadIdx.x;
    if (i < n) {
        int o = g_off[i] + g_bsum[i >> 10];
        g_off[i] = o;
        g_cursor[i] = o;
    }
}

// ---------------------------------------------------------------------------
// K4: fill per-dst edge lists (src ids, grouped by dst)
// ---------------------------------------------------------------------------
__global__ void fill_elist(const int* __restrict__ src,
                           const int* __restrict__ dst, int e) {
    int i = blockIdx.x * blockDim.x + threadIdx.x;
    if (i < e) {
        int d = dst[i];
        int pos = atomicAdd(&g_cursor[d], 1);
        g_elist[pos] = src[i];
    }
}

// ---------------------------------------------------------------------------
// K5: fused pull-aggregate + normalize + dual GEMM + bias + ReLU.
// Block = 256 threads, 16 nodes per block.
// Phase A (unchanged): 16 threads/node gather+sum neighbor rows (float4).
// Phase B (NEW): packed f32x2 FFMA. Accumulator holds (even-k, odd-k)
//   partial sums in one 64-bit reg. Feature pairs come free from the
//   float4 rows read as ulonglong2; weight pairs come free from a
//   k-pair-interleaved staging layout wS[k/2][j] = (W[k][j], W[k+1][j]).
//   Halves FFMA-pipe pressure with zero packing instructions.
// ---------------------------------------------------------------------------
__global__ __launch_bounds__(256)
void sage_pull(const float4* __restrict__ feat4,
               const float* __restrict__ W_self,
               const float* __restrict__ W_neigh,
               const float* __restrict__ bias,
               float* __restrict__ out,
               int n) {
    __shared__ u64t  sWs2[D / 2][D];   // 16 KB  (W_self k-pair packed)
    __shared__ u64t  sWn2[D / 2][D];   // 16 KB  (W_neigh k-pair packed)
    __shared__ float4 sf4[16][D4];     // 4 KB   self rows [node][kchunk]
    __shared__ float4 sh4[16][D4];     // 4 KB   normalized neighbor rows

    int tid = threadIdx.x;

    // stage weights k-pair-interleaved: float view, element (k>>1, j, k&1)
    {
        float* wsF = reinterpret_cast<float*>(sWs2);
        float* wnF = reinterpret_cast<float*>(sWn2);
        for (int i = tid; i < D * D; i += 256) {
            int k = i >> 6, j = i & 63;
            int idx = (k >> 1) * (2 * D) + j * 2 + (k & 1);
            wsF[idx] = W_self[i];
            wnF[idx] = W_neigh[i];
        }
    }

    // ---------- Phase A: gather ----------
    int nodeLocal = tid >> 4;        // 0..15
    int lane16    = tid & 15;        // float4 chunk within row
    int node      = blockIdx.x * 16 + nodeLocal;

    if (node < n) {
        int start = g_off[node];
        int g     = g_deg[node];
        float4 acc = make_float4(0.f, 0.f, 0.f, 0.f);
        int k = 0;
        for (; k + 4 <= g; k += 4) {            // unroll 4 for MLP
            int s0 = g_elist[start + k + 0];
            int s1 = g_elist[start + k + 1];
            int s2 = g_elist[start + k + 2];
            int s3 = g_elist[start + k + 3];
            float4 v0 = feat4[(size_t)s0 * D4 + lane16];
            float4 v1 = feat4[(size_t)s1 * D4 + lane16];
            float4 v2 = feat4[(size_t)s2 * D4 + lane16];
            float4 v3 = feat4[(size_t)s3 * D4 + lane16];
            acc.x += v0.x + v1.x + v2.x + v3.x;
            acc.y += v0.y + v1.y + v2.y + v3.y;
            acc.z += v0.z + v1.z + v2.z + v3.z;
            acc.w += v0.w + v1.w + v2.w + v3.w;
        }
        for (; k < g; k++) {
            int s0 = g_elist[start + k];
            float4 v0 = feat4[(size_t)s0 * D4 + lane16];
            acc.x += v0.x; acc.y += v0.y; acc.z += v0.z; acc.w += v0.w;
        }
        float inv = 1.0f / (float)max(g, 1);
        acc.x *= inv; acc.y *= inv; acc.z *= inv; acc.w *= inv;
        sh4[nodeLocal][lane16] = acc;
        sf4[nodeLocal][lane16] = feat4[(size_t)node * D4 + lane16];
    }
    __syncthreads();

    // ---------- Phase B: packed-f32x2 GEMM ----------
    int j   = tid & 63;              // output column
    int sub = tid >> 6;              // 0..3 -> nodes sub, sub+4, sub+8, sub+12

    const ulonglong2* f0p = reinterpret_cast<const ulonglong2*>(&sf4[sub + 0][0]);
    const ulonglong2* f1p = reinterpret_cast<const ulonglong2*>(&sf4[sub + 4][0]);
    const ulonglong2* f2p = reinterpret_cast<const ulonglong2*>(&sf4[sub + 8][0]);
    const ulonglong2* f3p = reinterpret_cast<const ulonglong2*>(&sf4[sub + 12][0]);
    const ulonglong2* h0p = reinterpret_cast<const ulonglong2*>(&sh4[sub + 0][0]);
    const ulonglong2* h1p = reinterpret_cast<const ulonglong2*>(&sh4[sub + 4][0]);
    const ulonglong2* h2p = reinterpret_cast<const ulonglong2*>(&sh4[sub + 8][0]);
    const ulonglong2* h3p = reinterpret_cast<const ulonglong2*>(&sh4[sub + 12][0]);

    // acc = (even-k partial, odd-k partial); init lo half with bias
    u64t binit = (u64t)__float_as_uint(bias[j]);
    u64t a0 = binit, a1 = binit, a2 = binit, a3 = binit;

#pragma unroll
    for (int kc = 0; kc < D4; kc++) {          // 16 chunks of 4 k's
        u64t ws0 = sWs2[2 * kc + 0][j];        // pairs (k, k+1)
        u64t ws1 = sWs2[2 * kc + 1][j];        // pairs (k+2, k+3)
        u64t wn0 = sWn2[2 * kc + 0][j];
        u64t wn1 = sWn2[2 * kc + 1][j];

        ulonglong2 f0 = f0p[kc], h0 = h0p[kc];
        ulonglong2 f1 = f1p[kc], h1 = h1p[kc];
        ulonglong2 f2 = f2p[kc], h2 = h2p[kc];
        ulonglong2 f3 = f3p[kc], h3 = h3p[kc];

        ffma2(a0, f0.x, ws0); ffma2(a0, f0.y, ws1);
        ffma2(a0, h0.x, wn0); ffma2(a0, h0.y, wn1);
        ffma2(a1, f1.x, ws0); ffma2(a1, f1.y, ws1);
        ffma2(a1, h1.x, wn0); ffma2(a1, h1.y, wn1);
        ffma2(a2, f2.x, ws0); ffma2(a2, f2.y, ws1);
        ffma2(a2, h2.x, wn0); ffma2(a2, h2.y, wn1);
        ffma2(a3, f3.x, ws0); ffma2(a3, f3.y, ws1);
        ffma2(a3, h3.x, wn0); ffma2(a3, h3.y, wn1);
    }

    int base = blockIdx.x * 16;
    int n0 = base + sub, n1 = base + sub + 4, n2 = base + sub + 8, n3 = base + sub + 12;
    float r0 = __uint_as_float((unsigned)a0) + __uint_as_float((unsigned)(a0 >> 32));
    float r1 = __uint_as_float((unsigned)a1) + __uint_as_float((unsigned)(a1 >> 32));
    float r2 = __uint_as_float((unsigned)a2) + __uint_as_float((unsigned)(a2 >> 32));
    float r3 = __uint_as_float((unsigned)a3) + __uint_as_float((unsigned)(a3 >> 32));
    if (n0 < n) out[(size_t)n0 * D + j] = fmaxf(r0, 0.f);
    if (n1 < n) out[(size_t)n1 * D + j] = fmaxf(r1, 0.f);
    if (n2 < n) out[(size_t)n2 * D + j] = fmaxf(r2, 0.f);
    if (n3 < n) out[(size_t)n3 * D + j] = fmaxf(r3, 0.f);
}

// ---------------------------------------------------------------------------
// Launch.  Inputs: feat[N*64] f32, src[E] i32, dst[E] i32,
//                  W_self[64*64] f32, W_neigh[64*64] f32, bias[64] f32
// ---------------------------------------------------------------------------
extern "C" void kernel_launch(void* const* d_in, const int* in_sizes, int n_in,
                              void* d_out, int out_size) {
    const float* feat    = (const float*)d_in[0];
    const int*   src     = (const int*)d_in[1];
    const int*   dst     = (const int*)d_in[2];
    const float* W_self  = (const float*)d_in[3];
    const float* W_neigh = (const float*)d_in[4];
    const float* bias    = (const float*)d_in[5];
    float*       out     = (float*)d_out;

    int n = in_sizes[0] / D;
    int e = in_sizes[1];

    int nb256  = (n + 255) / 256;
    int eb256  = (e + 255) / 256;
    int nScanB = (n + 1023) / 1024;

    zero_deg<<<nb256, 256>>>(n);
    count_deg<<<eb256, 256>>>(dst, e);
    scan_blocks<<<nScanB, 1024>>>(n);
    scan_bsums<<<1, 1024>>>(nScanB);
    scan_add<<<nb256, 256>>>(n);
    fill_elist<<<eb256, 256>>>(src, dst, e);
    sage_pull<<<(n + 15) / 16, 256>>>(reinterpret_cast<const float4*>(feat),
                                      W_self, W_neigh, bias, out, n);
}

// round 9
// speedup vs baseline: 1.4096x; 1.4096x over previous
#include <cuda_runtime.h>
#include <cuda_bf16.h>
#include <cstdint>

#define MAX_NODES 100000
#define MAX_EDGES 1600000
#define D 64
#define D4 (D / 4)
#define D2 (D / 2)

// ---------------------------------------------------------------------------
// Scratch (allocation-free rule -> device globals).
// ---------------------------------------------------------------------------
__device__ int g_deg[MAX_NODES];
__device__ int g_off[MAX_NODES];
__device__ int g_cursor[MAX_NODES];
__device__ int g_bsum[1024];
__device__ int g_elist[MAX_EDGES];
__device__ float2 g_h2[(size_t)MAX_NODES * D2];   // normalized neighbor means

// ---------------------------------------------------------------------------
// K1: zero degree counters
// ---------------------------------------------------------------------------
__global__ void zero_deg(int n) {
    int i = blockIdx.x * blockDim.x + threadIdx.x;
    if (i < n) g_deg[i] = 0;
}

// ---------------------------------------------------------------------------
// K2: count in-degree per dst (int32 indices)
// ---------------------------------------------------------------------------
__global__ void count_deg(const int* __restrict__ dst, int e) {
    int i = blockIdx.x * blockDim.x + threadIdx.x;
    if (i < e) atomicAdd(&g_deg[dst[i]], 1);
}

// ---------------------------------------------------------------------------
// K3a/b/c: exclusive scan of g_deg -> g_off  (1024 items per block)
// ---------------------------------------------------------------------------
__global__ __launch_bounds__(1024) void scan_blocks(int n) {
    __shared__ int s[1024];
    int tid = threadIdx.x;
    int i = blockIdx.x * 1024 + tid;
    int v = (i < n) ? g_deg[i] : 0;
    s[tid] = v;
    __syncthreads();
#pragma unroll
    for (int ofs = 1; ofs < 1024; ofs <<= 1) {
        int t = (tid >= ofs) ? s[tid - ofs] : 0;
        __syncthreads();
        s[tid] += t;
        __syncthreads();
    }
    if (i < n) g_off[i] = s[tid] - v;            // exclusive
    if (tid == 1023) g_bsum[blockIdx.x] = s[1023];
}

__global__ __launch_bounds__(1024) void scan_bsums(int nb) {
    __shared__ int s[1024];
    int tid = threadIdx.x;
    int v = (tid < nb) ? g_bsum[tid] : 0;
    s[tid] = v;
    __syncthreads();
#pragma unroll
    for (int ofs = 1; ofs < 1024; ofs <<= 1) {
        int t = (tid >= ofs) ? s[tid - ofs] : 0;
        __syncthreads();
        s[tid] += t;
        __syncthreads();
    }
    if (tid < nb) g_bsum[tid] = s[tid] - v;      // exclusive block offsets
}

__global__ void scan_add(int n) {
    int i = blockIdx.x * blockDim.x + threadIdx.x;
    if (i < n) {
        int o = g_off[i] + g_bsum[i >> 10];
        g_off[i] = o;
        g_cursor[i] = o;
    }
}

// ---------------------------------------------------------------------------
// K4: fill per-dst edge lists (src ids, grouped by dst)
// ---------------------------------------------------------------------------
__global__ void fill_elist(const int* __restrict__ src,
                           const int* __restrict__ dst, int e) {
    int i = blockIdx.x * blockDim.x + threadIdx.x;
    if (i < e) {
        int d = dst[i];
        int pos = atomicAdd(&g_cursor[d], 1);
        g_elist[pos] = src[i];
    }
}

// ---------------------------------------------------------------------------
// K5: gather. One warp per node; lane = float2 chunk (32 x 8B = full row).
// Per edge: one broadcast elist read + one fully-coalesced 256B row read.
// Zero intra-warp divergence; degree imbalance averages across the grid.
// Writes normalized neighbor mean to g_h2.
// ---------------------------------------------------------------------------
__global__ __launch_bounds__(256)
void gather_h(const float2* __restrict__ feat2, int n) {
    int warp = (blockIdx.x * 256 + threadIdx.x) >> 5;
    int lane = threadIdx.x & 31;
    if (warp >= n) return;
    int node  = warp;
    int start = g_off[node];
    int g     = g_deg[node];

    float2 acc = make_float2(0.f, 0.f);
    int k = 0;
    for (; k + 4 <= g; k += 4) {                 // unroll 4 for MLP
        int s0 = g_elist[start + k + 0];
        int s1 = g_elist[start + k + 1];
        int s2 = g_elist[start + k + 2];
        int s3 = g_elist[start + k + 3];
        float2 v0 = feat2[(size_t)s0 * D2 + lane];
        float2 v1 = feat2[(size_t)s1 * D2 + lane];
        float2 v2 = feat2[(size_t)s2 * D2 + lane];
        float2 v3 = feat2[(size_t)s3 * D2 + lane];
        acc.x += v0.x + v1.x + v2.x + v3.x;
        acc.y += v0.y + v1.y + v2.y + v3.y;
    }
    for (; k < g; k++) {
        int s0 = g_elist[start + k];
        float2 v0 = feat2[(size_t)s0 * D2 + lane];
        acc.x += v0.x; acc.y += v0.y;
    }
    float inv = 1.0f / (float)max(g, 1);
    acc.x *= inv; acc.y *= inv;
    g_h2[(size_t)node * D2 + lane] = acc;
}

// ---------------------------------------------------------------------------
// K6: dense dual GEMM + bias + ReLU. 16 nodes per block, 256 threads.
// Stage feat/h rows (coalesced, dense) + both W into shared, then the
// register-blocked fmaf loop (known-good R7 Phase B).
// ---------------------------------------------------------------------------
__global__ __launch_bounds__(256)
void sage_gemm(const float* __restrict__ feat,
               const float* __restrict__ W_self,
               const float* __restrict__ W_neigh,
               const float* __restrict__ bias,
               float* __restrict__ out,
               int n) {
    __shared__ float sWs[D][D];      // 16 KB
    __shared__ float sWn[D][D];      // 16 KB
    __shared__ float sf[16][D];      // 4 KB
    __shared__ float sh[16][D];      // 4 KB

    int tid = threadIdx.x;
    int base = blockIdx.x * 16;

    for (int i = tid; i < D * D; i += 256) {
        sWs[i >> 6][i & 63] = W_self[i];
        sWn[i >> 6][i & 63] = W_neigh[i];
    }

    // stage 16 node rows of feat and h (dense, coalesced)
    const float* hF = reinterpret_cast<const float*>(g_h2);
    int lim = (n - base) * D;                    // valid floats in this block
    for (int i = tid; i < 16 * D; i += 256) {
        bool ok = (i < lim);
        sf[0][i] = ok ? feat[(size_t)base * D + i] : 0.f;
        sh[0][i] = ok ? hF[(size_t)base * D + i] : 0.f;
    }
    __syncthreads();

    int j   = tid & 63;              // output column
    int sub = tid >> 6;              // 0..3 -> nodes sub, sub+4, sub+8, sub+12

    float b = bias[j];
    float a0 = b, a1 = b, a2 = b, a3 = b;

#pragma unroll
    for (int kc = 0; kc < D; kc += 4) {
        float ws0 = sWs[kc + 0][j], ws1 = sWs[kc + 1][j];
        float ws2 = sWs[kc + 2][j], ws3 = sWs[kc + 3][j];
        float wn0 = sWn[kc + 0][j], wn1 = sWn[kc + 1][j];
        float wn2 = sWn[kc + 2][j], wn3 = sWn[kc + 3][j];

        const float4 f0 = *reinterpret_cast<const float4*>(&sf[sub + 0][kc]);
        const float4 h0 = *reinterpret_cast<const float4*>(&sh[sub + 0][kc]);
        const float4 f1 = *reinterpret_cast<const float4*>(&sf[sub + 4][kc]);
        const float4 h1 = *reinterpret_cast<const float4*>(&sh[sub + 4][kc]);
        const float4 f2 = *reinterpret_cast<const float4*>(&sf[sub + 8][kc]);
        const float4 h2 = *reinterpret_cast<const float4*>(&sh[sub + 8][kc]);
        const float4 f3 = *reinterpret_cast<const float4*>(&sf[sub + 12][kc]);
        const float4 h3 = *reinterpret_cast<const float4*>(&sh[sub + 12][kc]);

        a0 = fmaf(f0.x, ws0, fmaf(f0.y, ws1, fmaf(f0.z, ws2, fmaf(f0.w, ws3, a0))));
        a0 = fmaf(h0.x, wn0, fmaf(h0.y, wn1, fmaf(h0.z, wn2, fmaf(h0.w, wn3, a0))));
        a1 = fmaf(f1.x, ws0, fmaf(f1.y, ws1, fmaf(f1.z, ws2, fmaf(f1.w, ws3, a1))));
        a1 = fmaf(h1.x, wn0, fmaf(h1.y, wn1, fmaf(h1.z, wn2, fmaf(h1.w, wn3, a1))));
        a2 = fmaf(f2.x, ws0, fmaf(f2.y, ws1, fmaf(f2.z, ws2, fmaf(f2.w, ws3, a2))));
        a2 = fmaf(h2.x, wn0, fmaf(h2.y, wn1, fmaf(h2.z, wn2, fmaf(h2.w, wn3, a2))));
        a3 = fmaf(f3.x, ws0, fmaf(f3.y, ws1, fmaf(f3.z, ws2, fmaf(f3.w, ws3, a3))));
        a3 = fmaf(h3.x, wn0, fmaf(h3.y, wn1, fmaf(h3.z, wn2, fmaf(h3.w, wn3, a3))));
    }

    int n0 = base + sub, n1 = base + sub + 4, n2 = base + sub + 8, n3 = base + sub + 12;
    if (n0 < n) out[(size_t)n0 * D + j] = fmaxf(a0, 0.f);
    if (n1 < n) out[(size_t)n1 * D + j] = fmaxf(a1, 0.f);
    if (n2 < n) out[(size_t)n2 * D + j] = fmaxf(a2, 0.f);
    if (n3 < n) out[(size_t)n3 * D + j] = fmaxf(a3, 0.f);
}

// ---------------------------------------------------------------------------
// Launch.  Inputs: feat[N*64] f32, src[E] i32, dst[E] i32,
//                  W_self[64*64] f32, W_neigh[64*64] f32, bias[64] f32
// ---------------------------------------------------------------------------
extern "C" void kernel_launch(void* const* d_in, const int* in_sizes, int n_in,
                              void* d_out, int out_size) {
    const float* feat    = (const float*)d_in[0];
    const int*   src     = (const int*)d_in[1];
    const int*   dst     = (const int*)d_in[2];
    const float* W_self  = (const float*)d_in[3];
    const float* W_neigh = (const float*)d_in[4];
    const float* bias    = (const float*)d_in[5];
    float*       out     = (float*)d_out;

    int n = in_sizes[0] / D;
    int e = in_sizes[1];

    int nb256  = (n + 255) / 256;
    int eb256  = (e + 255) / 256;
    int nScanB = (n + 1023) / 1024;

    zero_deg<<<nb256, 256>>>(n);
    count_deg<<<eb256, 256>>>(dst, e);
    scan_blocks<<<nScanB, 1024>>>(n);
    scan_bsums<<<1, 1024>>>(nScanB);
    scan_add<<<nb256, 256>>>(n);
    fill_elist<<<eb256, 256>>>(src, dst, e);

    int gwarps  = n;                              // one warp per node
    int gblocks = (gwarps + 7) / 8;               // 8 warps per block
    gather_h<<<gblocks, 256>>>(reinterpret_cast<const float2*>(feat), n);

    sage_gemm<<<(n + 15) / 16, 256>>>(feat, W_self, W_neigh, bias, out, n);
}

// round 10
// speedup vs baseline: 1.9186x; 1.3611x over previous
#include <cuda_runtime.h>
#include <cuda_bf16.h>
#include <cstdint>

#define MAX_NODES 100000
#define MAX_EDGES 1600000
#define D 64
#define D2 (D / 2)
#define D4c 16              // k-chunks of 4

// ---------------------------------------------------------------------------
// Scratch (allocation-free rule -> device globals).
// ---------------------------------------------------------------------------
__device__ int g_deg[MAX_NODES];
__device__ int g_off[MAX_NODES];
__device__ int g_cursor[MAX_NODES];
__device__ int g_bsum[1024];
__device__ int g_elist[MAX_EDGES];
__device__ float2 g_h2[(size_t)MAX_NODES * D2];   // normalized neighbor means

// ---------------------------------------------------------------------------
// K1: zero degree counters
// ---------------------------------------------------------------------------
__global__ void zero_deg(int n) {
    int i = blockIdx.x * blockDim.x + threadIdx.x;
    if (i < n) g_deg[i] = 0;
}

// ---------------------------------------------------------------------------
// K2: count in-degree per dst (int32 indices)
// ---------------------------------------------------------------------------
__global__ void count_deg(const int* __restrict__ dst, int e) {
    int i = blockIdx.x * blockDim.x + threadIdx.x;
    if (i < e) atomicAdd(&g_deg[dst[i]], 1);
}

// ---------------------------------------------------------------------------
// K3a/b/c: exclusive scan of g_deg -> g_off  (1024 items per block)
// ---------------------------------------------------------------------------
__global__ __launch_bounds__(1024) void scan_blocks(int n) {
    __shared__ int s[1024];
    int tid = threadIdx.x;
    int i = blockIdx.x * 1024 + tid;
    int v = (i < n) ? g_deg[i] : 0;
    s[tid] = v;
    __syncthreads();
#pragma unroll
    for (int ofs = 1; ofs < 1024; ofs <<= 1) {
        int t = (tid >= ofs) ? s[tid - ofs] : 0;
        __syncthreads();
        s[tid] += t;
        __syncthreads();
    }
    if (i < n) g_off[i] = s[tid] - v;            // exclusive
    if (tid == 1023) g_bsum[blockIdx.x] = s[1023];
}

__global__ __launch_bounds__(1024) void scan_bsums(int nb) {
    __shared__ int s[1024];
    int tid = threadIdx.x;
    int v = (tid < nb) ? g_bsum[tid] : 0;
    s[tid] = v;
    __syncthreads();
#pragma unroll
    for (int ofs = 1; ofs < 1024; ofs <<= 1) {
        int t = (tid >= ofs) ? s[tid - ofs] : 0;
        __syncthreads();
        s[tid] += t;
        __syncthreads();
    }
    if (tid < nb) g_bsum[tid] = s[tid] - v;      // exclusive block offsets
}

__global__ void scan_add(int n) {
    int i = blockIdx.x * blockDim.x + threadIdx.x;
    if (i < n) {
        int o = g_off[i] + g_bsum[i >> 10];
        g_off[i] = o;
        g_cursor[i] = o;
    }
}

// ---------------------------------------------------------------------------
// K4: fill per-dst edge lists (src ids, grouped by dst)
// ---------------------------------------------------------------------------
__global__ void fill_elist(const int* __restrict__ src,
                           const int* __restrict__ dst, int e) {
    int i = blockIdx.x * blockDim.x + threadIdx.x;
    if (i < e) {
        int d = dst[i];
        int pos = atomicAdd(&g_cursor[d], 1);
        g_elist[pos] = src[i];
    }
}

// ---------------------------------------------------------------------------
// K5: gather. One warp per node; lane = float2 chunk (32 x 8B = full row).
// ---------------------------------------------------------------------------
__global__ __launch_bounds__(256)
void gather_h(const float2* __restrict__ feat2, int n) {
    int warp = (blockIdx.x * 256 + threadIdx.x) >> 5;
    int lane = threadIdx.x & 31;
    if (warp >= n) return;
    int node  = warp;
    int start = g_off[node];
    int g     = g_deg[node];

    float2 acc = make_float2(0.f, 0.f);
    int k = 0;
    for (; k + 4 <= g; k += 4) {                 // unroll 4 for MLP
        int s0 = g_elist[start + k + 0];
        int s1 = g_elist[start + k + 1];
        int s2 = g_elist[start + k + 2];
        int s3 = g_elist[start + k + 3];
        float2 v0 = feat2[(size_t)s0 * D2 + lane];
        float2 v1 = feat2[(size_t)s1 * D2 + lane];
        float2 v2 = feat2[(size_t)s2 * D2 + lane];
        float2 v3 = feat2[(size_t)s3 * D2 + lane];
        acc.x += v0.x + v1.x + v2.x + v3.x;
        acc.y += v0.y + v1.y + v2.y + v3.y;
    }
    for (; k < g; k++) {
        int s0 = g_elist[start + k];
        float2 v0 = feat2[(size_t)s0 * D2 + lane];
        acc.x += v0.x; acc.y += v0.y;
    }
    float inv = 1.0f / (float)max(g, 1);
    acc.x *= inv; acc.y *= inv;
    g_h2[(size_t)node * D2 + lane] = acc;
}

// ---------------------------------------------------------------------------
// K6: register-blocked dual GEMM + bias + ReLU.
// 256 threads, 256 nodes/block (4 tiles of 64). Thread computes a 4-node x
// 4-col output tile. All SMEM layouts are k-chunk-major so warp reads are
// 16 consecutive float4s (conflict-free). Weights staged ONCE per block.
//   LDS per thread per kc: 16 x LDS.128 for 128 FMAs -> ~2 B/FMA.
// ---------------------------------------------------------------------------
#define NT_BLOCK 256            // nodes per block
#define NT_TILE  64             // nodes per inner tile
#define SROW 65                 // padded row (float4) for sF/sH staging

// dynamic smem partition (float4 units)
#define OFF_WS 0                       // [16][64]
#define OFF_WN (OFF_WS + D4c * 64)     // [16][64]
#define OFF_SF (OFF_WN + D4c * 64)     // [16][SROW]
#define OFF_SH (OFF_SF + D4c * SROW)   // [16][SROW]
#define SMEM_F4_TOTAL (OFF_SH + D4c * SROW)

__global__ __launch_bounds__(256)
void sage_gemm(const float4* __restrict__ feat4,
               const float* __restrict__ W_self,
               const float* __restrict__ W_neigh,
               const float* __restrict__ bias,
               float* __restrict__ out,
               int n) {
    extern __shared__ float4 smem[];
    float4* wS = smem + OFF_WS;         // wS[kc][j] = Ws[4kc..4kc+3][j]
    float4* wN = smem + OFF_WN;
    float4* sF = smem + OFF_SF;         // sF[kc][node]
    float4* sH = smem + OFF_SH;

    int tid = threadIdx.x;
    int jt  = tid & 15;                 // cols jt, jt+16, jt+32, jt+48
    int nt  = tid >> 4;                 // nodes nt, nt+16, nt+32, nt+48 (in tile)

    // ---- stage weights once per block (k-chunk packed per column) ----
    {
        float* wsF = reinterpret_cast<float*>(wS);
        float* wnF = reinterpret_cast<float*>(wN);
#pragma unroll
        for (int q = 0; q < 16; q++) {
            int i = tid + 256 * q;      // i over 4096 = 64k x 64j
            int k = i >> 6, j = i & 63;
            int idx = ((k >> 2) * 64 + j) * 4 + (k & 3);
            wsF[idx] = W_self[i];
            wnF[idx] = W_neigh[i];
        }
    }

    float bj[4];
#pragma unroll
    for (int c = 0; c < 4; c++) bj[c] = bias[jt + 16 * c];

    const float4* h4 = reinterpret_cast<const float4*>(g_h2);
    int blockBase = blockIdx.x * NT_BLOCK;

    for (int t = 0; t < NT_BLOCK / NT_TILE; t++) {
        int base = blockBase + t * NT_TILE;
        __syncthreads();                 // protect smem from previous tile use

        // ---- stage 64 nodes of feat and h, transposed to [kc][node] ----
#pragma unroll
        for (int q = 0; q < 4; q++) {
            int i = tid + 256 * q;       // i over 1024 = 64 nodes x 16 kc
            int node = i >> 4, kc = i & 15;
            int gn = base + node;
            float4 fz = make_float4(0.f, 0.f, 0.f, 0.f);
            float4 fv = fz, hv = fz;
            if (gn < n) {
                fv = feat4[(size_t)gn * D4c + kc];
                hv = h4[(size_t)gn * D4c + kc];
            }
            sF[kc * SROW + node] = fv;
            sH[kc * SROW + node] = hv;
        }
        __syncthreads();

        // ---- compute 4x4 tile ----
        float acc[4][4];
#pragma unroll
        for (int r = 0; r < 4; r++)
#pragma unroll
            for (int c = 0; c < 4; c++) acc[r][c] = bj[c];

#pragma unroll
        for (int kc = 0; kc < D4c; kc++) {
            float4 wsv[4], wnv[4], fv[4], hv[4];
#pragma unroll
            for (int c = 0; c < 4; c++) {
                wsv[c] = wS[kc * 64 + jt + 16 * c];
                wnv[c] = wN[kc * 64 + jt + 16 * c];
            }
#pragma unroll
            for (int r = 0; r < 4; r++) {
                fv[r] = sF[kc * SROW + nt + 16 * r];
                hv[r] = sH[kc * SROW + nt + 16 * r];
            }
#pragma unroll
            for (int r = 0; r < 4; r++) {
#pragma unroll
                for (int c = 0; c < 4; c++) {
                    float a = acc[r][c];
                    a = fmaf(fv[r].x, wsv[c].x, a);
                    a = fmaf(fv[r].y, wsv[c].y, a);
                    a = fmaf(fv[r].z, wsv[c].z, a);
                    a = fmaf(fv[r].w, wsv[c].w, a);
                    a = fmaf(hv[r].x, wnv[c].x, a);
                    a = fmaf(hv[r].y, wnv[c].y, a);
                    a = fmaf(hv[r].z, wnv[c].z, a);
                    a = fmaf(hv[r].w, wnv[c].w, a);
                    acc[r][c] = a;
                }
            }
        }

        // ---- store ----
#pragma unroll
        for (int r = 0; r < 4; r++) {
            int gn = base + nt + 16 * r;
            if (gn < n) {
#pragma unroll
                for (int c = 0; c < 4; c++) {
                    out[(size_t)gn * D + jt + 16 * c] = fmaxf(acc[r][c], 0.f);
                }
            }
        }
    }
}

// ---------------------------------------------------------------------------
// Launch.  Inputs: feat[N*64] f32, src[E] i32, dst[E] i32,
//                  W_self[64*64] f32, W_neigh[64*64] f32, bias[64] f32
// ---------------------------------------------------------------------------
extern "C" void kernel_launch(void* const* d_in, const int* in_sizes, int n_in,
                              void* d_out, int out_size) {
    const float* feat    = (const float*)d_in[0];
    const int*   src     = (const int*)d_in[1];
    const int*   dst     = (const int*)d_in[2];
    const float* W_self  = (const float*)d_in[3];
    const float* W_neigh = (const float*)d_in[4];
    const float* bias    = (const float*)d_in[5];
    float*       out     = (float*)d_out;

    int n = in_sizes[0] / D;
    int e = in_sizes[1];

    int nb256  = (n + 255) / 256;
    int eb256  = (e + 255) / 256;
    int nScanB = (n + 1023) / 1024;

    zero_deg<<<nb256, 256>>>(n);
    count_deg<<<eb256, 256>>>(dst, e);
    scan_blocks<<<nScanB, 1024>>>(n);
    scan_bsums<<<1, 1024>>>(nScanB);
    scan_add<<<nb256, 256>>>(n);
    fill_elist<<<eb256, 256>>>(src, dst, e);

    int gblocks = (n + 7) / 8;                    // one warp per node
    gather_h<<<gblocks, 256>>>(reinterpret_cast<const float2*>(feat), n);

    static int smem_set = 0;
    int smemBytes = SMEM_F4_TOTAL * sizeof(float4);   // ~66 KB
    if (!smem_set) {
        cudaFuncSetAttribute(sage_gemm, cudaFuncAttributeMaxDynamicSharedMemorySize,
                             smemBytes);
        smem_set = 1;
    }
    int gemmBlocks = (n + NT_BLOCK - 1) / NT_BLOCK;
    sage_gemm<<<gemmBlocks, 256, smemBytes>>>(
        reinterpret_cast<const float4*>(feat), W_self, W_neigh, bias, out, n);
}